// round 10
// baseline (speedup 1.0000x reference)
#include <cuda_runtime.h>
#include <cuda_fp16.h>
#include <cstdint>

#define NN 4096
#define CC 256
#define HH 8
#define DD 32
#define LOG2E 1.4426950408889634f

// scratch (device globals; no allocation allowed)
__device__ __half g_xh[NN * CC];          // x in f16
__device__ __half g_wt[4 * CC * CC];      // Wq,Wk,Wv,Wo transposed [n][k], f16
__device__ __half g_qh[HH * NN * DD];     // prescaled by scale*log2e
__device__ __half g_kh[HH * NN * DD];
__device__ __half g_vh[HH * NN * DD];
__device__ float g_part[2][NN * CC];      // un-normalized partial O
__device__ float g_lpart[2 * HH * NN];    // partial softmax denominators

// ---------------- helpers ----------------
__device__ __forceinline__ uint32_t f16pack(float lo, float hi) {
    uint32_t r;
    asm("cvt.rn.f16x2.f32 %0, %1, %2;" : "=r"(r) : "f"(hi), "f"(lo));
    return r;
}
__device__ __forceinline__ uint32_t ex2_f16x2(uint32_t x) {
    uint32_t r;
    asm("ex2.approx.f16x2 %0, %1;" : "=r"(r) : "r"(x));
    return r;
}
__device__ __forceinline__ uint32_t hadd2(uint32_t a, uint32_t b) {
    uint32_t r;
    asm("add.rn.f16x2 %0, %1, %2;" : "=r"(r) : "r"(a), "r"(b));
    return r;
}
__device__ __forceinline__ float2 h2f2(uint32_t h) {
    float lo, hi;
    asm("{.reg .f16 a,b; mov.b32 {a,b}, %2; cvt.f32.f16 %0, a; cvt.f32.f16 %1, b;}"
        : "=f"(lo), "=f"(hi) : "r"(h));
    return make_float2(lo, hi);
}
__device__ __forceinline__ void mma_f16(float* d, const uint32_t* a, const uint32_t* b) {
    asm volatile(
        "mma.sync.aligned.m16n8k16.row.col.f32.f16.f16.f32 "
        "{%0,%1,%2,%3}, {%4,%5,%6,%7}, {%8,%9}, {%0,%1,%2,%3};"
        : "+f"(d[0]), "+f"(d[1]), "+f"(d[2]), "+f"(d[3])
        : "r"(a[0]), "r"(a[1]), "r"(a[2]), "r"(a[3]), "r"(b[0]), "r"(b[1]));
}
__device__ __forceinline__ void ldmx4(uint32_t* r, uint32_t addr) {
    asm volatile("ldmatrix.sync.aligned.m8n8.x4.shared.b16 {%0,%1,%2,%3}, [%4];"
        : "=r"(r[0]), "=r"(r[1]), "=r"(r[2]), "=r"(r[3]) : "r"(addr));
}
__device__ __forceinline__ void ldmx4t(uint32_t* r, uint32_t addr) {
    asm volatile("ldmatrix.sync.aligned.m8n8.x4.trans.shared.b16 {%0,%1,%2,%3}, [%4];"
        : "=r"(r[0]), "=r"(r[1]), "=r"(r[2]), "=r"(r[3]) : "r"(addr));
}
__device__ __forceinline__ void cpa16(uint32_t d, const void* s) {
    asm volatile("{ .reg .u64 g; cvta.to.global.u64 g, %1; "
                 "cp.async.ca.shared.global [%0], [g], 16; }"
                 :: "r"(d), "l"(s) : "memory");
}
#define CP_COMMIT() asm volatile("cp.async.commit_group;" ::: "memory")
#define CP_WAIT(n)  asm volatile("cp.async.wait_group %0;" :: "n"(n) : "memory")

// ---------------- Kernel 0a: convert x -> f16 ----------------
__global__ void __launch_bounds__(256) cvt_x_kernel(const float* __restrict__ x)
{
    const int i = (blockIdx.x * 256 + threadIdx.x) * 4;
    float4 v = *(const float4*)&x[i];
    uint2 o;
    o.x = f16pack(v.x, v.y);
    o.y = f16pack(v.z, v.w);
    *(uint2*)&g_xh[i] = o;
}

// ---------------- Kernel 0b: transpose-convert W -> f16 [n][k] ----------------
__global__ void __launch_bounds__(256) cvt_w_kernel(
    const float* __restrict__ Wq, const float* __restrict__ Wk,
    const float* __restrict__ Wv, const float* __restrict__ Wo)
{
    __shared__ float t[32][33];
    const int z = blockIdx.z;
    const float* W = (z == 0) ? Wq : (z == 1) ? Wk : (z == 2) ? Wv : Wo;
    const int k0 = blockIdx.y * 32, n0 = blockIdx.x * 32;
    const int tx = threadIdx.x & 31, ty = threadIdx.x >> 5;  // 32x8
#pragma unroll
    for (int i = 0; i < 4; i++)
        t[ty + 8 * i][tx] = W[(size_t)(k0 + ty + 8 * i) * CC + n0 + tx];
    __syncthreads();
    __half* out = &g_wt[(size_t)z * CC * CC];
#pragma unroll
    for (int i = 0; i < 4; i++)
        out[(size_t)(n0 + ty + 8 * i) * CC + k0 + tx] = __float2half(t[tx][ty + 8 * i]);
}

// ---------------- Kernel 1: f16 mma QKV GEMM, cp.async pipelined ----------------
// grid (4, 64, 3), 128 threads (2x2 warps of 32x32). BK=32, double-buffered.
#define QSTR 20  /* words per 32-f16 row (16 data + 4 pad) -> conflict-free ldmatrix */

__global__ void __launch_bounds__(128) qkv_mma_kernel(
    const float* __restrict__ bq, const float* __restrict__ bk,
    const float* __restrict__ bv, const float* __restrict__ scale_p)
{
    __shared__ uint32_t As[2][64 * QSTR];
    __shared__ uint32_t Bs[2][64 * QSTR];

    const int z = blockIdx.z;
    const float* bia = (z == 0) ? bq : (z == 1) ? bk : bv;
    __half* out = (z == 0) ? g_qh : (z == 1) ? g_kh : g_vh;
    const float s = (z == 0) ? (*scale_p) * LOG2E : 1.0f;

    const int row0 = blockIdx.y * 64;
    const int col0 = blockIdx.x * 64;
    const int tid = threadIdx.x;
    const int w = tid >> 5;
    const int lane = tid & 31;
    const int gid = lane >> 2;
    const int tig = lane & 3;
    const int m0 = (w & 1) * 32;
    const int n0 = (w >> 1) * 32;

    const __half* Ag = &g_xh[(size_t)row0 * CC];
    const __half* Bg = &g_wt[(size_t)z * CC * CC + (size_t)col0 * CC];
    const uint32_t asb = (uint32_t)__cvta_generic_to_shared(As);
    const uint32_t bsb = (uint32_t)__cvta_generic_to_shared(Bs);

    const int sr = tid >> 1, sc = tid & 1;
    float acc[2][4][4] = {};

    {
        uint32_t da = asb + (sr * QSTR + sc * 8) * 4;
        cpa16(da, Ag + sr * CC + sc * 16);
        cpa16(da + 16, Ag + sr * CC + sc * 16 + 8);
        uint32_t db = bsb + (sr * QSTR + sc * 8) * 4;
        cpa16(db, Bg + sr * CC + sc * 16);
        cpa16(db + 16, Bg + sr * CC + sc * 16 + 8);
        CP_COMMIT();
    }

    int b = 0;
    for (int it = 0; it < 8; it++) {
        if (it < 7) {
            const int kn = (it + 1) * 32;
            uint32_t da = asb + ((b ^ 1) * 64 * QSTR + sr * QSTR + sc * 8) * 4;
            cpa16(da, Ag + sr * CC + kn + sc * 16);
            cpa16(da + 16, Ag + sr * CC + kn + sc * 16 + 8);
            uint32_t db = bsb + ((b ^ 1) * 64 * QSTR + sr * QSTR + sc * 8) * 4;
            cpa16(db, Bg + sr * CC + kn + sc * 16);
            cpa16(db + 16, Bg + sr * CC + kn + sc * 16 + 8);
            CP_COMMIT();
            CP_WAIT(1);
        } else {
            CP_WAIT(0);
        }
        __syncthreads();

        uint32_t a[2][2][4];
#pragma unroll
        for (int mi = 0; mi < 2; mi++)
#pragma unroll
            for (int ks = 0; ks < 2; ks++)
                ldmx4(a[mi][ks], asb + (b * 64 * QSTR + (m0 + mi * 16 + (lane & 15)) * QSTR
                                        + ks * 8 + (lane >> 4) * 4) * 4);
        uint32_t bf[4][4];
#pragma unroll
        for (int ni = 0; ni < 4; ni++)
            ldmx4(bf[ni], bsb + (b * 64 * QSTR + (n0 + ni * 8 + (lane & 7)) * QSTR
                                 + (lane >> 3) * 4) * 4);
#pragma unroll
        for (int ks = 0; ks < 2; ks++)
#pragma unroll
            for (int mi = 0; mi < 2; mi++)
#pragma unroll
                for (int ni = 0; ni < 4; ni++)
                    mma_f16(acc[mi][ni], a[mi][ks], &bf[ni][2 * ks]);
        __syncthreads();
        b ^= 1;
    }

#pragma unroll
    for (int mi = 0; mi < 2; mi++) {
        const int row = row0 + m0 + mi * 16 + gid;
#pragma unroll
        for (int ni = 0; ni < 4; ni++) {
            const int col = col0 + n0 + ni * 8 + 2 * tig;
            const int h = col >> 5, d = col & 31;
            const float b0 = bia[col], b1 = bia[col + 1];
            uint32_t w0 = f16pack((acc[mi][ni][0] + b0) * s, (acc[mi][ni][1] + b1) * s);
            uint32_t w1 = f16pack((acc[mi][ni][2] + b0) * s, (acc[mi][ni][3] + b1) * s);
            *(uint32_t*)&out[((size_t)h * NN + row) * DD + d] = w0;
            *(uint32_t*)&out[((size_t)h * NN + row + 8) * DD + d] = w1;
        }
    }
}

// ---------------- Kernel 2: f16 mma flash attention, split-K, cp.async pipelined ----------------
// l computed via HADD2 (alu pipe) with per-chunk f16x2 accumulators upconverted
// to f32 each chunk — keeps the tensor pipe for real work only.
#define QT 128
#define KT 128
#define NCHUNK (NN / KT)
#define SPLIT 2
#define NITER (NCHUNK / SPLIT)
#define KVSTR 20

__global__ void __launch_bounds__(128, 5) attn_mma_kernel()
{
    __shared__ uint32_t Ksm[2][KT * KVSTR];
    __shared__ uint32_t Vsm[2][KT * KVSTR];

    const int tid = threadIdx.x;
    const int w = tid >> 5;
    const int lane = tid & 31;
    const int gid = lane >> 2;
    const int tig = lane & 3;
    const int h = blockIdx.y;
    const int q0 = blockIdx.x * QT;
    const int sp = blockIdx.z;

    const uint32_t ksb = (uint32_t)__cvta_generic_to_shared(Ksm);
    const uint32_t vsb = (uint32_t)__cvta_generic_to_shared(Vsm);

    const __half* Kg = &g_kh[((size_t)h * NN + tid) * DD];
    const __half* Vg = &g_vh[((size_t)h * NN + tid) * DD];
    const uint32_t kdst = ksb + tid * KVSTR * 4;
    const uint32_t vdst = vsb + tid * KVSTR * 4;

    // Q fragments (f16, scale*log2e folded)
    uint32_t qa[2][2][4];
#pragma unroll
    for (int mi = 0; mi < 2; mi++) {
        const int r0 = q0 + w * 32 + mi * 16 + gid;
        const uint32_t* p0 = (const uint32_t*)&g_qh[((size_t)h * NN + r0) * DD];
        const uint32_t* p1 = (const uint32_t*)&g_qh[((size_t)h * NN + r0 + 8) * DD];
#pragma unroll
        for (int ks = 0; ks < 2; ks++) {
            qa[mi][ks][0] = p0[8 * ks + tig];
            qa[mi][ks][1] = p1[8 * ks + tig];
            qa[mi][ks][2] = p0[8 * ks + tig + 4];
            qa[mi][ks][3] = p1[8 * ks + tig + 4];
        }
    }

    // prologue: stage chunk sp into buf 0
    {
        const size_t off = (size_t)sp * KT * DD;
#pragma unroll
        for (int j = 0; j < 4; j++) {
            cpa16(kdst + 16 * j, Kg + off + 8 * j);
            cpa16(vdst + 16 * j, Vg + off + 8 * j);
        }
        CP_COMMIT();
    }

    float O[2][4][4] = {};
    float lf[2][2] = {};   // f32 denominators, per mi per row-half
    int b = 0;

    for (int it = 0; it < NITER; it++) {
        if (it < NITER - 1) {
            const size_t off = (size_t)(sp + (it + 1) * SPLIT) * KT * DD;
            const uint32_t bo2 = (b ^ 1) * KT * KVSTR * 4;
#pragma unroll
            for (int j = 0; j < 4; j++) {
                cpa16(kdst + bo2 + 16 * j, Kg + off + 8 * j);
                cpa16(vdst + bo2 + 16 * j, Vg + off + 8 * j);
            }
            CP_COMMIT();
            CP_WAIT(1);
        } else {
            CP_WAIT(0);
        }
        __syncthreads();

        const uint32_t kbase = ksb + b * KT * KVSTR * 4;
        const uint32_t vbase = vsb + b * KT * KVSTR * 4;

        uint32_t lc[2][2] = {{0u, 0u}, {0u, 0u}};  // per-chunk f16x2 accum

#pragma unroll
        for (int sub = 0; sub < 4; sub++) {
            const int n0 = sub * 32;

            uint32_t kb[4][4];
#pragma unroll
            for (int ni = 0; ni < 4; ni++)
                ldmx4(kb[ni], kbase + ((n0 + ni * 8 + (lane & 7)) * KVSTR + (lane >> 3) * 4) * 4);

            float S[2][4][4] = {};
#pragma unroll
            for (int ks = 0; ks < 2; ks++)
#pragma unroll
                for (int mi = 0; mi < 2; mi++)
#pragma unroll
                    for (int ni = 0; ni < 4; ni++)
                        mma_f16(S[mi][ni], qa[mi][ks], &kb[ni][2 * ks]);

            uint32_t ep[2][4][2];
#pragma unroll
            for (int mi = 0; mi < 2; mi++) {
#pragma unroll
                for (int ni = 0; ni < 4; ni++) {
                    ep[mi][ni][0] = ex2_f16x2(f16pack(S[mi][ni][0], S[mi][ni][1]));
                    ep[mi][ni][1] = ex2_f16x2(f16pack(S[mi][ni][2], S[mi][ni][3]));
                }
                // l accumulation on the alu pipe (tensor stays free)
                lc[mi][0] = hadd2(lc[mi][0],
                                  hadd2(hadd2(ep[mi][0][0], ep[mi][1][0]),
                                        hadd2(ep[mi][2][0], ep[mi][3][0])));
                lc[mi][1] = hadd2(lc[mi][1],
                                  hadd2(hadd2(ep[mi][0][1], ep[mi][1][1]),
                                        hadd2(ep[mi][2][1], ep[mi][3][1])));
            }

            uint32_t vb[4][4];
#pragma unroll
            for (int nd = 0; nd < 4; nd++)
                ldmx4t(vb[nd], vbase + ((n0 + lane) * KVSTR + nd * 4) * 4);

#pragma unroll
            for (int g = 0; g < 2; g++) {
                uint32_t pa[2][4];
#pragma unroll
                for (int mi = 0; mi < 2; mi++) {
                    pa[mi][0] = ep[mi][2 * g][0];
                    pa[mi][1] = ep[mi][2 * g][1];
                    pa[mi][2] = ep[mi][2 * g + 1][0];
                    pa[mi][3] = ep[mi][2 * g + 1][1];
                }
#pragma unroll
                for (int nd = 0; nd < 4; nd++)
#pragma unroll
                    for (int mi = 0; mi < 2; mi++)
                        mma_f16(O[mi][nd], pa[mi], &vb[nd][2 * g]);
            }
        }

        // upconvert per-chunk l to f32
#pragma unroll
        for (int mi = 0; mi < 2; mi++) {
            float2 a0 = h2f2(lc[mi][0]);
            float2 a1 = h2f2(lc[mi][1]);
            lf[mi][0] += a0.x + a0.y;
            lf[mi][1] += a1.x + a1.y;
        }

        __syncthreads();
        b ^= 1;
    }

    // reduce l over tig (4 threads per row cover disjoint key columns)
#pragma unroll
    for (int mi = 0; mi < 2; mi++)
#pragma unroll
        for (int hf = 0; hf < 2; hf++) {
            float v = lf[mi][hf];
            v += __shfl_xor_sync(0xffffffffu, v, 1);
            v += __shfl_xor_sync(0xffffffffu, v, 2);
            lf[mi][hf] = v;
        }

    float* part = g_part[sp];
#pragma unroll
    for (int mi = 0; mi < 2; mi++) {
        const int r0 = q0 + w * 32 + mi * 16 + gid;
        if (tig == 0) {
            g_lpart[sp * HH * NN + h * NN + r0] = lf[mi][0];
            g_lpart[sp * HH * NN + h * NN + r0 + 8] = lf[mi][1];
        }
#pragma unroll
        for (int nd = 0; nd < 4; nd++) {
            const int col = h * DD + nd * 8 + 2 * tig;
            *(float2*)&part[(size_t)r0 * CC + col] = make_float2(O[mi][nd][0], O[mi][nd][1]);
            *(float2*)&part[(size_t)(r0 + 8) * CC + col] = make_float2(O[mi][nd][2], O[mi][nd][3]);
        }
    }
}

// ---------------- Kernel 3: mma out-proj + residual + LayerNorm ----------------
#define PMS_STR 132
#define PBS_STR 12

__global__ void __launch_bounds__(256) proj_mma_kernel(
    const float* __restrict__ x, const float* __restrict__ bo,
    const float* __restrict__ gamma, const float* __restrict__ beta,
    float* __restrict__ out)
{
    __shared__ uint32_t MS[32 * PMS_STR];
    __shared__ uint32_t BS[2][CC * PBS_STR];
    __shared__ float red[2][4][16][2];

    const int tid = threadIdx.x;
    const int w = tid >> 5;
    const int lane = tid & 31;
    const int gid = lane >> 2;
    const int tig = lane & 3;
    const int mh = w & 1;
    const int nw = w >> 1;
    const int m0 = mh * 16;
    const int n0 = nw * 64;
    const int row0 = blockIdx.x * 32;

    const uint32_t msb = (uint32_t)__cvta_generic_to_shared(MS);
    const uint32_t bsb = (uint32_t)__cvta_generic_to_shared(BS);
    const __half* Wg = &g_wt[3 * CC * CC];

    {
        uint32_t db = bsb + tid * PBS_STR * 4;
        cpa16(db, Wg + (size_t)tid * CC);
        cpa16(db + 16, Wg + (size_t)tid * CC + 8);
        CP_COMMIT();
    }

    for (int f = tid; f < 32 * 64; f += 256) {
        const int r = f >> 6;
        const int cq = (f & 63) * 4;
        const int node = row0 + r;
        const int h = cq >> 5;
        const float rl = 1.f / (g_lpart[h * NN + node] + g_lpart[HH * NN + h * NN + node]);
        float4 a = *(const float4*)&g_part[0][(size_t)node * CC + cq];
        float4 b4 = *(const float4*)&g_part[1][(size_t)node * CC + cq];
        MS[r * PMS_STR + cq / 2]     = f16pack((a.x + b4.x) * rl, (a.y + b4.y) * rl);
        MS[r * PMS_STR + cq / 2 + 1] = f16pack((a.z + b4.z) * rl, (a.w + b4.w) * rl);
    }

    float acc[8][4] = {};
    int b = 0;
    for (int it = 0; it < 16; it++) {
        if (it < 15) {
            const int kn = (it + 1) * 16;
            uint32_t db = bsb + ((b ^ 1) * CC * PBS_STR + tid * PBS_STR) * 4;
            cpa16(db, Wg + (size_t)tid * CC + kn);
            cpa16(db + 16, Wg + (size_t)tid * CC + kn + 8);
            CP_COMMIT();
            CP_WAIT(1);
        } else {
            CP_WAIT(0);
        }
        __syncthreads();

        uint32_t a[4];
        ldmx4(a, msb + ((m0 + (lane & 15)) * PMS_STR + it * 8 + (lane >> 4) * 4) * 4);

        uint32_t bf[4][4];
#pragma unroll
        for (int nj = 0; nj < 4; nj++)
            ldmx4(bf[nj], bsb + (b * CC * PBS_STR
                                 + (n0 + nj * 16 + (lane & 7) + (lane >> 4) * 8) * PBS_STR
                                 + ((lane >> 3) & 1) * 4) * 4);
#pragma unroll
        for (int nj = 0; nj < 4; nj++) {
            mma_f16(acc[2 * nj],     a, &bf[nj][0]);
            mma_f16(acc[2 * nj + 1], a, &bf[nj][2]);
        }
        __syncthreads();
        b ^= 1;
    }

    const int node0 = row0 + m0;
    float y[8][4];
    float s0 = 0.f, q0s = 0.f, s1 = 0.f, q1s = 0.f;
#pragma unroll
    for (int ni = 0; ni < 8; ni++) {
        const int c0 = n0 + ni * 8 + 2 * tig;
        float2 x0 = *(const float2*)&x[(size_t)(node0 + gid) * CC + c0];
        float2 x1 = *(const float2*)&x[(size_t)(node0 + gid + 8) * CC + c0];
        const float b0 = bo[c0], b1 = bo[c0 + 1];
        y[ni][0] = acc[ni][0] + b0 + x0.x;
        y[ni][1] = acc[ni][1] + b1 + x0.y;
        y[ni][2] = acc[ni][2] + b0 + x1.x;
        y[ni][3] = acc[ni][3] + b1 + x1.y;
        s0 += y[ni][0] + y[ni][1];
        s1 += y[ni][2] + y[ni][3];
        q0s = fmaf(y[ni][0], y[ni][0], fmaf(y[ni][1], y[ni][1], q0s));
        q1s = fmaf(y[ni][2], y[ni][2], fmaf(y[ni][3], y[ni][3], q1s));
    }
#pragma unroll
    for (int off = 1; off <= 2; off <<= 1) {
        s0 += __shfl_xor_sync(0xffffffffu, s0, off);
        s1 += __shfl_xor_sync(0xffffffffu, s1, off);
        q0s += __shfl_xor_sync(0xffffffffu, q0s, off);
        q1s += __shfl_xor_sync(0xffffffffu, q1s, off);
    }
    if (tig == 0) {
        red[mh][nw][gid][0] = s0;     red[mh][nw][gid][1] = q0s;
        red[mh][nw][gid + 8][0] = s1; red[mh][nw][gid + 8][1] = q1s;
    }
    __syncthreads();
    float sum0 = 0.f, sq0 = 0.f, sum1 = 0.f, sq1 = 0.f;
#pragma unroll
    for (int j = 0; j < 4; j++) {
        sum0 += red[mh][j][gid][0];     sq0 += red[mh][j][gid][1];
        sum1 += red[mh][j][gid + 8][0]; sq1 += red[mh][j][gid + 8][1];
    }
    const float mu0 = sum0 * (1.f / 256.f);
    const float mu1 = sum1 * (1.f / 256.f);
    const float rs0 = rsqrtf(sq0 * (1.f / 256.f) - mu0 * mu0 + 1e-5f);
    const float rs1 = rsqrtf(sq1 * (1.f / 256.f) - mu1 * mu1 + 1e-5f);
#pragma unroll
    for (int ni = 0; ni < 8; ni++) {
        const int c0 = n0 + ni * 8 + 2 * tig;
        const float g0 = gamma[c0], g1 = gamma[c0 + 1];
        const float be0 = beta[c0], be1 = beta[c0 + 1];
        *(float2*)&out[(size_t)(node0 + gid) * CC + c0] =
            make_float2((y[ni][0] - mu0) * rs0 * g0 + be0,
                        (y[ni][1] - mu0) * rs0 * g1 + be1);
        *(float2*)&out[(size_t)(node0 + gid + 8) * CC + c0] =
            make_float2((y[ni][2] - mu1) * rs1 * g0 + be0,
                        (y[ni][3] - mu1) * rs1 * g1 + be1);
    }
}

// ---------------- launch ----------------
extern "C" void kernel_launch(void* const* d_in, const int* in_sizes, int n_in,
                              void* d_out, int out_size)
{
    const float* x     = (const float*)d_in[0];
    const float* Wq    = (const float*)d_in[1];
    const float* bq    = (const float*)d_in[2];
    const float* Wk    = (const float*)d_in[3];
    const float* bk    = (const float*)d_in[4];
    const float* Wv    = (const float*)d_in[5];
    const float* bv    = (const float*)d_in[6];
    const float* scale = (const float*)d_in[7];
    const float* Wo    = (const float*)d_in[8];
    const float* bo    = (const float*)d_in[9];
    const float* gamma = (const float*)d_in[10];
    const float* beta  = (const float*)d_in[11];
    float* out = (float*)d_out;

    cvt_x_kernel<<<NN * CC / 1024, 256>>>(x);
    cvt_w_kernel<<<dim3(8, 8, 4), 256>>>(Wq, Wk, Wv, Wo);
    qkv_mma_kernel<<<dim3(CC / 64, NN / 64, 3), 128>>>(bq, bk, bv, scale);
    attn_mma_kernel<<<dim3(NN / QT, HH, SPLIT), 128>>>();
    proj_mma_kernel<<<NN / 32, 256>>>(x, bo, gamma, beta, out);
}

// round 11
// speedup vs baseline: 1.0747x; 1.0747x over previous
#include <cuda_runtime.h>
#include <cuda_fp16.h>
#include <cstdint>

#define NN 4096
#define CC 256
#define HH 8
#define DD 32
#define LOG2E 1.4426950408889634f

// scratch (device globals; no allocation allowed)
__device__ __half g_xh[NN * CC];          // x in f16
__device__ __half g_wt[4 * CC * CC];      // Wq,Wk,Wv,Wo transposed [n][k], f16
__device__ __half g_qh[HH * NN * DD];     // prescaled by scale*log2e
__device__ __half g_kh[HH * NN * DD];
__device__ __half g_vh[HH * NN * DD];
__device__ float g_part[2][NN * CC];      // un-normalized partial O
__device__ float g_lpart[2 * HH * NN];    // partial softmax denominators

// ---------------- helpers ----------------
__device__ __forceinline__ uint32_t f16pack(float lo, float hi) {
    uint32_t r;
    asm("cvt.rn.f16x2.f32 %0, %1, %2;" : "=r"(r) : "f"(hi), "f"(lo));
    return r;
}
__device__ __forceinline__ uint32_t ex2_f16x2(uint32_t x) {
    uint32_t r;
    asm("ex2.approx.f16x2 %0, %1;" : "=r"(r) : "r"(x));
    return r;
}
__device__ __forceinline__ void mma_f16(float* d, const uint32_t* a, const uint32_t* b) {
    asm volatile(
        "mma.sync.aligned.m16n8k16.row.col.f32.f16.f16.f32 "
        "{%0,%1,%2,%3}, {%4,%5,%6,%7}, {%8,%9}, {%0,%1,%2,%3};"
        : "+f"(d[0]), "+f"(d[1]), "+f"(d[2]), "+f"(d[3])
        : "r"(a[0]), "r"(a[1]), "r"(a[2]), "r"(a[3]), "r"(b[0]), "r"(b[1]));
}
__device__ __forceinline__ void ldmx4(uint32_t* r, uint32_t addr) {
    asm volatile("ldmatrix.sync.aligned.m8n8.x4.shared.b16 {%0,%1,%2,%3}, [%4];"
        : "=r"(r[0]), "=r"(r[1]), "=r"(r[2]), "=r"(r[3]) : "r"(addr));
}
__device__ __forceinline__ void ldmx4t(uint32_t* r, uint32_t addr) {
    asm volatile("ldmatrix.sync.aligned.m8n8.x4.trans.shared.b16 {%0,%1,%2,%3}, [%4];"
        : "=r"(r[0]), "=r"(r[1]), "=r"(r[2]), "=r"(r[3]) : "r"(addr));
}
__device__ __forceinline__ void cpa16(uint32_t d, const void* s) {
    asm volatile("{ .reg .u64 g; cvta.to.global.u64 g, %1; "
                 "cp.async.ca.shared.global [%0], [g], 16; }"
                 :: "r"(d), "l"(s) : "memory");
}
#define CP_COMMIT() asm volatile("cp.async.commit_group;" ::: "memory")
#define CP_WAIT(n)  asm volatile("cp.async.wait_group %0;" :: "n"(n) : "memory")

// ---------------- Kernel 0a: convert x -> f16 ----------------
__global__ void __launch_bounds__(256) cvt_x_kernel(const float* __restrict__ x)
{
    const int i = (blockIdx.x * 256 + threadIdx.x) * 4;
    float4 v = *(const float4*)&x[i];
    uint2 o;
    o.x = f16pack(v.x, v.y);
    o.y = f16pack(v.z, v.w);
    *(uint2*)&g_xh[i] = o;
}

// ---------------- Kernel 0b: transpose-convert W -> f16 [n][k] ----------------
__global__ void __launch_bounds__(256) cvt_w_kernel(
    const float* __restrict__ Wq, const float* __restrict__ Wk,
    const float* __restrict__ Wv, const float* __restrict__ Wo)
{
    __shared__ float t[32][33];
    const int z = blockIdx.z;
    const float* W = (z == 0) ? Wq : (z == 1) ? Wk : (z == 2) ? Wv : Wo;
    const int k0 = blockIdx.y * 32, n0 = blockIdx.x * 32;
    const int tx = threadIdx.x & 31, ty = threadIdx.x >> 5;  // 32x8
#pragma unroll
    for (int i = 0; i < 4; i++)
        t[ty + 8 * i][tx] = W[(size_t)(k0 + ty + 8 * i) * CC + n0 + tx];
    __syncthreads();
    __half* out = &g_wt[(size_t)z * CC * CC];
#pragma unroll
    for (int i = 0; i < 4; i++)
        out[(size_t)(n0 + ty + 8 * i) * CC + k0 + tx] = __float2half(t[tx][ty + 8 * i]);
}

// ---------------- Kernel 1: f16 mma QKV GEMM, cp.async pipelined ----------------
#define QSTR 20

__global__ void __launch_bounds__(128) qkv_mma_kernel(
    const float* __restrict__ bq, const float* __restrict__ bk,
    const float* __restrict__ bv, const float* __restrict__ scale_p)
{
    __shared__ uint32_t As[2][64 * QSTR];
    __shared__ uint32_t Bs[2][64 * QSTR];

    const int z = blockIdx.z;
    const float* bia = (z == 0) ? bq : (z == 1) ? bk : bv;
    __half* out = (z == 0) ? g_qh : (z == 1) ? g_kh : g_vh;
    const float s = (z == 0) ? (*scale_p) * LOG2E : 1.0f;

    const int row0 = blockIdx.y * 64;
    const int col0 = blockIdx.x * 64;
    const int tid = threadIdx.x;
    const int w = tid >> 5;
    const int lane = tid & 31;
    const int gid = lane >> 2;
    const int tig = lane & 3;
    const int m0 = (w & 1) * 32;
    const int n0 = (w >> 1) * 32;

    const __half* Ag = &g_xh[(size_t)row0 * CC];
    const __half* Bg = &g_wt[(size_t)z * CC * CC + (size_t)col0 * CC];
    const uint32_t asb = (uint32_t)__cvta_generic_to_shared(As);
    const uint32_t bsb = (uint32_t)__cvta_generic_to_shared(Bs);

    const int sr = tid >> 1, sc = tid & 1;
    float acc[2][4][4] = {};

    {
        uint32_t da = asb + (sr * QSTR + sc * 8) * 4;
        cpa16(da, Ag + sr * CC + sc * 16);
        cpa16(da + 16, Ag + sr * CC + sc * 16 + 8);
        uint32_t db = bsb + (sr * QSTR + sc * 8) * 4;
        cpa16(db, Bg + sr * CC + sc * 16);
        cpa16(db + 16, Bg + sr * CC + sc * 16 + 8);
        CP_COMMIT();
    }

    int b = 0;
    for (int it = 0; it < 8; it++) {
        if (it < 7) {
            const int kn = (it + 1) * 32;
            uint32_t da = asb + ((b ^ 1) * 64 * QSTR + sr * QSTR + sc * 8) * 4;
            cpa16(da, Ag + sr * CC + kn + sc * 16);
            cpa16(da + 16, Ag + sr * CC + kn + sc * 16 + 8);
            uint32_t db = bsb + ((b ^ 1) * 64 * QSTR + sr * QSTR + sc * 8) * 4;
            cpa16(db, Bg + sr * CC + kn + sc * 16);
            cpa16(db + 16, Bg + sr * CC + kn + sc * 16 + 8);
            CP_COMMIT();
            CP_WAIT(1);
        } else {
            CP_WAIT(0);
        }
        __syncthreads();

        uint32_t a[2][2][4];
#pragma unroll
        for (int mi = 0; mi < 2; mi++)
#pragma unroll
            for (int ks = 0; ks < 2; ks++)
                ldmx4(a[mi][ks], asb + (b * 64 * QSTR + (m0 + mi * 16 + (lane & 15)) * QSTR
                                        + ks * 8 + (lane >> 4) * 4) * 4);
        uint32_t bf[4][4];
#pragma unroll
        for (int ni = 0; ni < 4; ni++)
            ldmx4(bf[ni], bsb + (b * 64 * QSTR + (n0 + ni * 8 + (lane & 7)) * QSTR
                                 + (lane >> 3) * 4) * 4);
#pragma unroll
        for (int ks = 0; ks < 2; ks++)
#pragma unroll
            for (int mi = 0; mi < 2; mi++)
#pragma unroll
                for (int ni = 0; ni < 4; ni++)
                    mma_f16(acc[mi][ni], a[mi][ks], &bf[ni][2 * ks]);
        __syncthreads();
        b ^= 1;
    }

#pragma unroll
    for (int mi = 0; mi < 2; mi++) {
        const int row = row0 + m0 + mi * 16 + gid;
#pragma unroll
        for (int ni = 0; ni < 4; ni++) {
            const int col = col0 + n0 + ni * 8 + 2 * tig;
            const int h = col >> 5, d = col & 31;
            const float b0 = bia[col], b1 = bia[col + 1];
            uint32_t w0 = f16pack((acc[mi][ni][0] + b0) * s, (acc[mi][ni][1] + b1) * s);
            uint32_t w1 = f16pack((acc[mi][ni][2] + b0) * s, (acc[mi][ni][3] + b1) * s);
            *(uint32_t*)&out[((size_t)h * NN + row) * DD + d] = w0;
            *(uint32_t*)&out[((size_t)h * NN + row + 8) * DD + d] = w1;
        }
    }
}

// ---------------- Kernel 2: f16 mma flash attention, split-K ----------------
// K|V interleaved: one 128B row per key (K dims in 16B chunks 0-3, V in 4-7),
// chunk c of row r stored at c^(r&7) -> zero padding, conflict-free ldmatrix.
// Double-buffered = 32KB total smem -> 4 CTAs/SM, single wave for 512 CTAs.
// l computed by PV mma against a CONSTANT ones fragment (no smem, no extra LDSM).
#define QT 128
#define KT 128
#define NCHUNK (NN / KT)
#define SPLIT 2
#define NITER (NCHUNK / SPLIT)

__global__ void __launch_bounds__(128) attn_mma_kernel()
{
    __shared__ uint32_t KV[2][KT * 32];   // 2 x 16KB

    const int tid = threadIdx.x;
    const int w = tid >> 5;
    const int lane = tid & 31;
    const int gid = lane >> 2;
    const int tig = lane & 3;
    const int h = blockIdx.y;
    const int q0 = blockIdx.x * QT;
    const int sp = blockIdx.z;

    const uint32_t kvb = (uint32_t)__cvta_generic_to_shared(KV);

    const __half* Kg = &g_kh[((size_t)h * NN + tid) * DD];
    const __half* Vg = &g_vh[((size_t)h * NN + tid) * DD];
    const uint32_t rowdst = kvb + tid * 128;
    const int rsw = tid & 7;

    // Q fragments (f16, scale*log2e folded)
    uint32_t qa[2][2][4];
#pragma unroll
    for (int mi = 0; mi < 2; mi++) {
        const int r0 = q0 + w * 32 + mi * 16 + gid;
        const uint32_t* p0 = (const uint32_t*)&g_qh[((size_t)h * NN + r0) * DD];
        const uint32_t* p1 = (const uint32_t*)&g_qh[((size_t)h * NN + r0 + 8) * DD];
#pragma unroll
        for (int ks = 0; ks < 2; ks++) {
            qa[mi][ks][0] = p0[8 * ks + tig];
            qa[mi][ks][1] = p1[8 * ks + tig];
            qa[mi][ks][2] = p0[8 * ks + tig + 4];
            qa[mi][ks][3] = p1[8 * ks + tig + 4];
        }
    }

    // ones B-fragment for the l column (n-col 0 all ones): constant per thread
    const uint32_t onesf = (gid == 0) ? 0x3C003C00u : 0u;
    const uint32_t onesb[2] = {onesf, onesf};

    // prologue: stage chunk sp into buf 0
    {
        const size_t off = (size_t)sp * KT * DD;
#pragma unroll
        for (int c = 0; c < 4; c++) {
            cpa16(rowdst + ((c ^ rsw) << 4), Kg + off + 8 * c);
            cpa16(rowdst + (((4 + c) ^ rsw) << 4), Vg + off + 8 * c);
        }
        CP_COMMIT();
    }

    float O[2][5][4] = {};   // nd=4 holds l
    int b = 0;

    for (int it = 0; it < NITER; it++) {
        if (it < NITER - 1) {
            const size_t off = (size_t)(sp + (it + 1) * SPLIT) * KT * DD;
            const uint32_t bo2 = rowdst + (b ^ 1) * (KT * 32 * 4);
#pragma unroll
            for (int c = 0; c < 4; c++) {
                cpa16(bo2 + ((c ^ rsw) << 4), Kg + off + 8 * c);
                cpa16(bo2 + (((4 + c) ^ rsw) << 4), Vg + off + 8 * c);
            }
            CP_COMMIT();
            CP_WAIT(1);
        } else {
            CP_WAIT(0);
        }
        __syncthreads();

        const uint32_t base = kvb + b * (KT * 32 * 4);

#pragma unroll
        for (int sub = 0; sub < 4; sub++) {
            const int n0 = sub * 32;

            // K fragments: 4 matrices (16B chunks 0-3), rows = keys
            uint32_t kb[4][4];
#pragma unroll
            for (int ni = 0; ni < 4; ni++) {
                const int kr = n0 + ni * 8 + (lane & 7);
                ldmx4(kb[ni], base + kr * 128 + (((lane >> 3) ^ (kr & 7)) << 4));
            }

            float S[2][4][4] = {};
#pragma unroll
            for (int ks = 0; ks < 2; ks++)
#pragma unroll
                for (int mi = 0; mi < 2; mi++)
#pragma unroll
                    for (int ni = 0; ni < 4; ni++)
                        mma_f16(S[mi][ni], qa[mi][ks], &kb[ni][2 * ks]);

            uint32_t ep[2][4][2];
#pragma unroll
            for (int mi = 0; mi < 2; mi++)
#pragma unroll
                for (int ni = 0; ni < 4; ni++) {
                    ep[mi][ni][0] = ex2_f16x2(f16pack(S[mi][ni][0], S[mi][ni][1]));
                    ep[mi][ni][1] = ex2_f16x2(f16pack(S[mi][ni][2], S[mi][ni][3]));
                }

            // V^T fragments (trans): V chunk nd at logical 4+nd, rows = keys
            uint32_t vb[4][4];
#pragma unroll
            for (int nd = 0; nd < 4; nd++) {
                const int vr = n0 + lane;
                ldmx4t(vb[nd], base + vr * 128 + ((((4 + nd)) ^ (vr & 7)) << 4));
            }

#pragma unroll
            for (int g = 0; g < 2; g++) {
                uint32_t pa[2][4];
#pragma unroll
                for (int mi = 0; mi < 2; mi++) {
                    pa[mi][0] = ep[mi][2 * g][0];
                    pa[mi][1] = ep[mi][2 * g][1];
                    pa[mi][2] = ep[mi][2 * g + 1][0];
                    pa[mi][3] = ep[mi][2 * g + 1][1];
                }
#pragma unroll
                for (int nd = 0; nd < 4; nd++)
#pragma unroll
                    for (int mi = 0; mi < 2; mi++)
                        mma_f16(O[mi][nd], pa[mi], &vb[nd][2 * g]);
                // l column (constant ones fragment, no load)
#pragma unroll
                for (int mi = 0; mi < 2; mi++)
                    mma_f16(O[mi][4], pa[mi], onesb);
            }
        }
        __syncthreads();
        b ^= 1;
    }

    float* part = g_part[sp];
#pragma unroll
    for (int mi = 0; mi < 2; mi++) {
        const int r0 = q0 + w * 32 + mi * 16 + gid;
        if (tig == 0) {
            g_lpart[sp * HH * NN + h * NN + r0] = O[mi][4][0];
            g_lpart[sp * HH * NN + h * NN + r0 + 8] = O[mi][4][2];
        }
#pragma unroll
        for (int nd = 0; nd < 4; nd++) {
            const int col = h * DD + nd * 8 + 2 * tig;
            *(float2*)&part[(size_t)r0 * CC + col] = make_float2(O[mi][nd][0], O[mi][nd][1]);
            *(float2*)&part[(size_t)(r0 + 8) * CC + col] = make_float2(O[mi][nd][2], O[mi][nd][3]);
        }
    }
}

// ---------------- Kernel 3: mma out-proj + residual + LayerNorm ----------------
#define PMS_STR 132
#define PBS_STR 12

__global__ void __launch_bounds__(256) proj_mma_kernel(
    const float* __restrict__ x, const float* __restrict__ bo,
    const float* __restrict__ gamma, const float* __restrict__ beta,
    float* __restrict__ out)
{
    __shared__ uint32_t MS[32 * PMS_STR];
    __shared__ uint32_t BS[2][CC * PBS_STR];
    __shared__ float red[2][4][16][2];

    const int tid = threadIdx.x;
    const int w = tid >> 5;
    const int lane = tid & 31;
    const int gid = lane >> 2;
    const int tig = lane & 3;
    const int mh = w & 1;
    const int nw = w >> 1;
    const int m0 = mh * 16;
    const int n0 = nw * 64;
    const int row0 = blockIdx.x * 32;

    const uint32_t msb = (uint32_t)__cvta_generic_to_shared(MS);
    const uint32_t bsb = (uint32_t)__cvta_generic_to_shared(BS);
    const __half* Wg = &g_wt[3 * CC * CC];

    {
        uint32_t db = bsb + tid * PBS_STR * 4;
        cpa16(db, Wg + (size_t)tid * CC);
        cpa16(db + 16, Wg + (size_t)tid * CC + 8);
        CP_COMMIT();
    }

    for (int f = tid; f < 32 * 64; f += 256) {
        const int r = f >> 6;
        const int cq = (f & 63) * 4;
        const int node = row0 + r;
        const int h = cq >> 5;
        const float rl = 1.f / (g_lpart[h * NN + node] + g_lpart[HH * NN + h * NN + node]);
        float4 a = *(const float4*)&g_part[0][(size_t)node * CC + cq];
        float4 b4 = *(const float4*)&g_part[1][(size_t)node * CC + cq];
        MS[r * PMS_STR + cq / 2]     = f16pack((a.x + b4.x) * rl, (a.y + b4.y) * rl);
        MS[r * PMS_STR + cq / 2 + 1] = f16pack((a.z + b4.z) * rl, (a.w + b4.w) * rl);
    }

    float acc[8][4] = {};
    int b = 0;
    for (int it = 0; it < 16; it++) {
        if (it < 15) {
            const int kn = (it + 1) * 16;
            uint32_t db = bsb + ((b ^ 1) * CC * PBS_STR + tid * PBS_STR) * 4;
            cpa16(db, Wg + (size_t)tid * CC + kn);
            cpa16(db + 16, Wg + (size_t)tid * CC + kn + 8);
            CP_COMMIT();
            CP_WAIT(1);
        } else {
            CP_WAIT(0);
        }
        __syncthreads();

        uint32_t a[4];
        ldmx4(a, msb + ((m0 + (lane & 15)) * PMS_STR + it * 8 + (lane >> 4) * 4) * 4);

        uint32_t bf[4][4];
#pragma unroll
        for (int nj = 0; nj < 4; nj++)
            ldmx4(bf[nj], bsb + (b * CC * PBS_STR
                                 + (n0 + nj * 16 + (lane & 7) + (lane >> 4) * 8) * PBS_STR
                                 + ((lane >> 3) & 1) * 4) * 4);
#pragma unroll
        for (int nj = 0; nj < 4; nj++) {
            mma_f16(acc[2 * nj],     a, &bf[nj][0]);
            mma_f16(acc[2 * nj + 1], a, &bf[nj][2]);
        }
        __syncthreads();
        b ^= 1;
    }

    const int node0 = row0 + m0;
    float y[8][4];
    float s0 = 0.f, q0s = 0.f, s1 = 0.f, q1s = 0.f;
#pragma unroll
    for (int ni = 0; ni < 8; ni++) {
        const int c0 = n0 + ni * 8 + 2 * tig;
        float2 x0 = *(const float2*)&x[(size_t)(node0 + gid) * CC + c0];
        float2 x1 = *(const float2*)&x[(size_t)(node0 + gid + 8) * CC + c0];
        const float b0 = bo[c0], b1 = bo[c0 + 1];
        y[ni][0] = acc[ni][0] + b0 + x0.x;
        y[ni][1] = acc[ni][1] + b1 + x0.y;
        y[ni][2] = acc[ni][2] + b0 + x1.x;
        y[ni][3] = acc[ni][3] + b1 + x1.y;
        s0 += y[ni][0] + y[ni][1];
        s1 += y[ni][2] + y[ni][3];
        q0s = fmaf(y[ni][0], y[ni][0], fmaf(y[ni][1], y[ni][1], q0s));
        q1s = fmaf(y[ni][2], y[ni][2], fmaf(y[ni][3], y[ni][3], q1s));
    }
#pragma unroll
    for (int off = 1; off <= 2; off <<= 1) {
        s0 += __shfl_xor_sync(0xffffffffu, s0, off);
        s1 += __shfl_xor_sync(0xffffffffu, s1, off);
        q0s += __shfl_xor_sync(0xffffffffu, q0s, off);
        q1s += __shfl_xor_sync(0xffffffffu, q1s, off);
    }
    if (tig == 0) {
        red[mh][nw][gid][0] = s0;     red[mh][nw][gid][1] = q0s;
        red[mh][nw][gid + 8][0] = s1; red[mh][nw][gid + 8][1] = q1s;
    }
    __syncthreads();
    float sum0 = 0.f, sq0 = 0.f, sum1 = 0.f, sq1 = 0.f;
#pragma unroll
    for (int j = 0; j < 4; j++) {
        sum0 += red[mh][j][gid][0];     sq0 += red[mh][j][gid][1];
        sum1 += red[mh][j][gid + 8][0]; sq1 += red[mh][j][gid + 8][1];
    }
    const float mu0 = sum0 * (1.f / 256.f);
    const float mu1 = sum1 * (1.f / 256.f);
    const float rs0 = rsqrtf(sq0 * (1.f / 256.f) - mu0 * mu0 + 1e-5f);
    const float rs1 = rsqrtf(sq1 * (1.f / 256.f) - mu1 * mu1 + 1e-5f);
#pragma unroll
    for (int ni = 0; ni < 8; ni++) {
        const int c0 = n0 + ni * 8 + 2 * tig;
        const float g0 = gamma[c0], g1 = gamma[c0 + 1];
        const float be0 = beta[c0], be1 = beta[c0 + 1];
        *(float2*)&out[(size_t)(node0 + gid) * CC + c0] =
            make_float2((y[ni][0] - mu0) * rs0 * g0 + be0,
                        (y[ni][1] - mu0) * rs0 * g1 + be1);
        *(float2*)&out[(size_t)(node0 + gid + 8) * CC + c0] =
            make_float2((y[ni][2] - mu1) * rs1 * g0 + be0,
                        (y[ni][3] - mu1) * rs1 * g1 + be1);
    }
}

// ---------------- launch ----------------
extern "C" void kernel_launch(void* const* d_in, const int* in_sizes, int n_in,
                              void* d_out, int out_size)
{
    const float* x     = (const float*)d_in[0];
    const float* Wq    = (const float*)d_in[1];
    const float* bq    = (const float*)d_in[2];
    const float* Wk    = (const float*)d_in[3];
    const float* bk    = (const float*)d_in[4];
    const float* Wv    = (const float*)d_in[5];
    const float* bv    = (const float*)d_in[6];
    const float* scale = (const float*)d_in[7];
    const float* Wo    = (const float*)d_in[8];
    const float* bo    = (const float*)d_in[9];
    const float* gamma = (const float*)d_in[10];
    const float* beta  = (const float*)d_in[11];
    float* out = (float*)d_out;

    cvt_x_kernel<<<NN * CC / 1024, 256>>>(x);
    cvt_w_kernel<<<dim3(8, 8, 4), 256>>>(Wq, Wk, Wv, Wo);
    qkv_mma_kernel<<<dim3(CC / 64, NN / 64, 3), 128>>>(bq, bk, bv, scale);
    attn_mma_kernel<<<dim3(NN / QT, HH, SPLIT), 128>>>();
    proj_mma_kernel<<<NN / 32, 256>>>(x, bo, gamma, beta, out);
}

// round 14
// speedup vs baseline: 1.0777x; 1.0029x over previous
#include <cuda_runtime.h>
#include <cuda_fp16.h>
#include <cstdint>

#define NN 4096
#define CC 256
#define HH 8
#define DD 32
#define LOG2E 1.4426950408889634f

// scratch (device globals; no allocation allowed)
__device__ __half g_xh[NN * CC];          // x in f16
__device__ __half g_wt[4 * CC * CC];      // Wq,Wk,Wv,Wo transposed [n][k], f16
__device__ __half g_qh[HH * NN * DD];     // prescaled by scale*log2e
__device__ __half g_kh[HH * NN * DD];
__device__ __half g_vh[HH * NN * DD];
__device__ float g_part[2][NN * CC];      // un-normalized partial O
__device__ float g_lpart[2 * HH * NN];    // partial softmax denominators

// ---------------- helpers ----------------
__device__ __forceinline__ uint32_t f16pack(float lo, float hi) {
    uint32_t r;
    asm("cvt.rn.f16x2.f32 %0, %1, %2;" : "=r"(r) : "f"(hi), "f"(lo));
    return r;
}
__device__ __forceinline__ uint32_t ex2_f16x2(uint32_t x) {
    uint32_t r;
    asm("ex2.approx.f16x2 %0, %1;" : "=r"(r) : "r"(x));
    return r;
}
__device__ __forceinline__ void mma_f16(float* d, const uint32_t* a, const uint32_t* b) {
    asm volatile(
        "mma.sync.aligned.m16n8k16.row.col.f32.f16.f16.f32 "
        "{%0,%1,%2,%3}, {%4,%5,%6,%7}, {%8,%9}, {%0,%1,%2,%3};"
        : "+f"(d[0]), "+f"(d[1]), "+f"(d[2]), "+f"(d[3])
        : "r"(a[0]), "r"(a[1]), "r"(a[2]), "r"(a[3]), "r"(b[0]), "r"(b[1]));
}
__device__ __forceinline__ void ldmx4(uint32_t* r, uint32_t addr) {
    asm volatile("ldmatrix.sync.aligned.m8n8.x4.shared.b16 {%0,%1,%2,%3}, [%4];"
        : "=r"(r[0]), "=r"(r[1]), "=r"(r[2]), "=r"(r[3]) : "r"(addr));
}
__device__ __forceinline__ void ldmx4t(uint32_t* r, uint32_t addr) {
    asm volatile("ldmatrix.sync.aligned.m8n8.x4.trans.shared.b16 {%0,%1,%2,%3}, [%4];"
        : "=r"(r[0]), "=r"(r[1]), "=r"(r[2]), "=r"(r[3]) : "r"(addr));
}
__device__ __forceinline__ void cpa16(uint32_t d, const void* s) {
    asm volatile("{ .reg .u64 g; cvta.to.global.u64 g, %1; "
                 "cp.async.ca.shared.global [%0], [g], 16; }"
                 :: "r"(d), "l"(s) : "memory");
}
#define CP_COMMIT() asm volatile("cp.async.commit_group;" ::: "memory")
#define CP_WAIT(n)  asm volatile("cp.async.wait_group %0;" :: "n"(n) : "memory")

// ---------------- Kernel 0a: convert x -> f16 ----------------
__global__ void __launch_bounds__(256) cvt_x_kernel(const float* __restrict__ x)
{
    const int i = (blockIdx.x * 256 + threadIdx.x) * 4;
    float4 v = *(const float4*)&x[i];
    uint2 o;
    o.x = f16pack(v.x, v.y);
    o.y = f16pack(v.z, v.w);
    *(uint2*)&g_xh[i] = o;
}

// ---------------- Kernel 0b: transpose-convert W -> f16 [n][k] ----------------
__global__ void __launch_bounds__(256) cvt_w_kernel(
    const float* __restrict__ Wq, const float* __restrict__ Wk,
    const float* __restrict__ Wv, const float* __restrict__ Wo)
{
    __shared__ float t[32][33];
    const int z = blockIdx.z;
    const float* W = (z == 0) ? Wq : (z == 1) ? Wk : (z == 2) ? Wv : Wo;
    const int k0 = blockIdx.y * 32, n0 = blockIdx.x * 32;
    const int tx = threadIdx.x & 31, ty = threadIdx.x >> 5;  // 32x8
#pragma unroll
    for (int i = 0; i < 4; i++)
        t[ty + 8 * i][tx] = W[(size_t)(k0 + ty + 8 * i) * CC + n0 + tx];
    __syncthreads();
    __half* out = &g_wt[(size_t)z * CC * CC];
#pragma unroll
    for (int i = 0; i < 4; i++)
        out[(size_t)(n0 + ty + 8 * i) * CC + k0 + tx] = __float2half(t[tx][ty + 8 * i]);
}

// ---------------- Kernel 1: f16 mma QKV GEMM, cp.async pipelined ----------------
#define QSTR 20

__global__ void __launch_bounds__(128) qkv_mma_kernel(
    const float* __restrict__ bq, const float* __restrict__ bk,
    const float* __restrict__ bv, const float* __restrict__ scale_p)
{
    __shared__ uint32_t As[2][64 * QSTR];
    __shared__ uint32_t Bs[2][64 * QSTR];

    const int z = blockIdx.z;
    const float* bia = (z == 0) ? bq : (z == 1) ? bk : bv;
    __half* out = (z == 0) ? g_qh : (z == 1) ? g_kh : g_vh;
    const float s = (z == 0) ? (*scale_p) * LOG2E : 1.0f;

    const int row0 = blockIdx.y * 64;
    const int col0 = blockIdx.x * 64;
    const int tid = threadIdx.x;
    const int w = tid >> 5;
    const int lane = tid & 31;
    const int gid = lane >> 2;
    const int tig = lane & 3;
    const int m0 = (w & 1) * 32;
    const int n0 = (w >> 1) * 32;

    const __half* Ag = &g_xh[(size_t)row0 * CC];
    const __half* Bg = &g_wt[(size_t)z * CC * CC + (size_t)col0 * CC];
    const uint32_t asb = (uint32_t)__cvta_generic_to_shared(As);
    const uint32_t bsb = (uint32_t)__cvta_generic_to_shared(Bs);

    const int sr = tid >> 1, sc = tid & 1;
    float acc[2][4][4] = {};

    {
        uint32_t da = asb + (sr * QSTR + sc * 8) * 4;
        cpa16(da, Ag + sr * CC + sc * 16);
        cpa16(da + 16, Ag + sr * CC + sc * 16 + 8);
        uint32_t db = bsb + (sr * QSTR + sc * 8) * 4;
        cpa16(db, Bg + sr * CC + sc * 16);
        cpa16(db + 16, Bg + sr * CC + sc * 16 + 8);
        CP_COMMIT();
    }

    int b = 0;
    for (int it = 0; it < 8; it++) {
        if (it < 7) {
            const int kn = (it + 1) * 32;
            uint32_t da = asb + ((b ^ 1) * 64 * QSTR + sr * QSTR + sc * 8) * 4;
            cpa16(da, Ag + sr * CC + kn + sc * 16);
            cpa16(da + 16, Ag + sr * CC + kn + sc * 16 + 8);
            uint32_t db = bsb + ((b ^ 1) * 64 * QSTR + sr * QSTR + sc * 8) * 4;
            cpa16(db, Bg + sr * CC + kn + sc * 16);
            cpa16(db + 16, Bg + sr * CC + kn + sc * 16 + 8);
            CP_COMMIT();
            CP_WAIT(1);
        } else {
            CP_WAIT(0);
        }
        __syncthreads();

        uint32_t a[2][2][4];
#pragma unroll
        for (int mi = 0; mi < 2; mi++)
#pragma unroll
            for (int ks = 0; ks < 2; ks++)
                ldmx4(a[mi][ks], asb + (b * 64 * QSTR + (m0 + mi * 16 + (lane & 15)) * QSTR
                                        + ks * 8 + (lane >> 4) * 4) * 4);
        uint32_t bf[4][4];
#pragma unroll
        for (int ni = 0; ni < 4; ni++)
            ldmx4(bf[ni], bsb + (b * 64 * QSTR + (n0 + ni * 8 + (lane & 7)) * QSTR
                                 + (lane >> 3) * 4) * 4);
#pragma unroll
        for (int ks = 0; ks < 2; ks++)
#pragma unroll
            for (int mi = 0; mi < 2; mi++)
#pragma unroll
                for (int ni = 0; ni < 4; ni++)
                    mma_f16(acc[mi][ni], a[mi][ks], &bf[ni][2 * ks]);
        __syncthreads();
        b ^= 1;
    }

#pragma unroll
    for (int mi = 0; mi < 2; mi++) {
        const int row = row0 + m0 + mi * 16 + gid;
#pragma unroll
        for (int ni = 0; ni < 4; ni++) {
            const int col = col0 + n0 + ni * 8 + 2 * tig;
            const int h = col >> 5, d = col & 31;
            const float b0 = bia[col], b1 = bia[col + 1];
            uint32_t w0 = f16pack((acc[mi][ni][0] + b0) * s, (acc[mi][ni][1] + b1) * s);
            uint32_t w1 = f16pack((acc[mi][ni][2] + b0) * s, (acc[mi][ni][3] + b1) * s);
            *(uint32_t*)&out[((size_t)h * NN + row) * DD + d] = w0;
            *(uint32_t*)&out[((size_t)h * NN + row + 8) * DD + d] = w1;
        }
    }
}

// ---------------- Kernel 2: f16 mma flash attention, split-K ----------------
// K|V interleaved, XOR swizzle, 32KB double-buffered smem. l via constant ones
// B-fragment. Reg cap 128 -> 4 CTAs/SM (single wave of 512 CTAs at 37 SM-groups).
#define QT 128
#define KT 128
#define NCHUNK (NN / KT)
#define SPLIT 2
#define NITER (NCHUNK / SPLIT)

__global__ void __launch_bounds__(128, 4) attn_mma_kernel()
{
    __shared__ uint32_t KV[2][KT * 32];   // 2 x 16KB

    const int tid = threadIdx.x;
    const int w = tid >> 5;
    const int lane = tid & 31;
    const int gid = lane >> 2;
    const int tig = lane & 3;
    const int h = blockIdx.y;
    const int q0 = blockIdx.x * QT;
    const int sp = blockIdx.z;

    const uint32_t kvb = (uint32_t)__cvta_generic_to_shared(KV);

    const __half* Kg = &g_kh[((size_t)h * NN + tid) * DD];
    const __half* Vg = &g_vh[((size_t)h * NN + tid) * DD];
    const uint32_t rowdst = kvb + tid * 128;
    const int rsw = tid & 7;

    // Q fragments (f16, scale*log2e folded)
    uint32_t qa[2][2][4];
#pragma unroll
    for (int mi = 0; mi < 2; mi++) {
        const int r0 = q0 + w * 32 + mi * 16 + gid;
        const uint32_t* p0 = (const uint32_t*)&g_qh[((size_t)h * NN + r0) * DD];
        const uint32_t* p1 = (const uint32_t*)&g_qh[((size_t)h * NN + r0 + 8) * DD];
#pragma unroll
        for (int ks = 0; ks < 2; ks++) {
            qa[mi][ks][0] = p0[8 * ks + tig];
            qa[mi][ks][1] = p1[8 * ks + tig];
            qa[mi][ks][2] = p0[8 * ks + tig + 4];
            qa[mi][ks][3] = p1[8 * ks + tig + 4];
        }
    }

    // ones B-fragment for the l column (n-col 0 all ones): constant per thread
    const uint32_t onesf = (gid == 0) ? 0x3C003C00u : 0u;
    const uint32_t onesb[2] = {onesf, onesf};

    // prologue: stage chunk sp into buf 0
    {
        const size_t off = (size_t)sp * KT * DD;
#pragma unroll
        for (int c = 0; c < 4; c++) {
            cpa16(rowdst + ((c ^ rsw) << 4), Kg + off + 8 * c);
            cpa16(rowdst + (((4 + c) ^ rsw) << 4), Vg + off + 8 * c);
        }
        CP_COMMIT();
    }

    float O[2][5][4] = {};   // nd=4 holds l
    int b = 0;

    for (int it = 0; it < NITER; it++) {
        if (it < NITER - 1) {
            const size_t off = (size_t)(sp + (it + 1) * SPLIT) * KT * DD;
            const uint32_t bo2 = rowdst + (b ^ 1) * (KT * 32 * 4);
#pragma unroll
            for (int c = 0; c < 4; c++) {
                cpa16(bo2 + ((c ^ rsw) << 4), Kg + off + 8 * c);
                cpa16(bo2 + (((4 + c) ^ rsw) << 4), Vg + off + 8 * c);
            }
            CP_COMMIT();
            CP_WAIT(1);
        } else {
            CP_WAIT(0);
        }
        __syncthreads();

        const uint32_t base = kvb + b * (KT * 32 * 4);

#pragma unroll
        for (int sub = 0; sub < 4; sub++) {
            const int n0 = sub * 32;

            // K fragments: 4 matrices (16B chunks 0-3), rows = keys
            uint32_t kb[4][4];
#pragma unroll
            for (int ni = 0; ni < 4; ni++) {
                const int kr = n0 + ni * 8 + (lane & 7);
                ldmx4(kb[ni], base + kr * 128 + (((lane >> 3) ^ (kr & 7)) << 4));
            }

            // per-mi: S then immediately ex2 -> ep (halves live S registers)
            uint32_t ep[2][4][2];
#pragma unroll
            for (int mi = 0; mi < 2; mi++) {
                float S[4][4] = {};
#pragma unroll
                for (int ks = 0; ks < 2; ks++)
#pragma unroll
                    for (int ni = 0; ni < 4; ni++)
                        mma_f16(S[ni], qa[mi][ks], &kb[ni][2 * ks]);
#pragma unroll
                for (int ni = 0; ni < 4; ni++) {
                    ep[mi][ni][0] = ex2_f16x2(f16pack(S[ni][0], S[ni][1]));
                    ep[mi][ni][1] = ex2_f16x2(f16pack(S[ni][2], S[ni][3]));
                }
            }

            // V^T fragments (trans): V chunk nd at logical 4+nd, rows = keys
            uint32_t vb[4][4];
#pragma unroll
            for (int nd = 0; nd < 4; nd++) {
                const int vr = n0 + lane;
                ldmx4t(vb[nd], base + vr * 128 + ((((4 + nd)) ^ (vr & 7)) << 4));
            }

#pragma unroll
            for (int g = 0; g < 2; g++) {
                uint32_t pa[2][4];
#pragma unroll
                for (int mi = 0; mi < 2; mi++) {
                    pa[mi][0] = ep[mi][2 * g][0];
                    pa[mi][1] = ep[mi][2 * g][1];
                    pa[mi][2] = ep[mi][2 * g + 1][0];
                    pa[mi][3] = ep[mi][2 * g + 1][1];
                }
#pragma unroll
                for (int nd = 0; nd < 4; nd++)
#pragma unroll
                    for (int mi = 0; mi < 2; mi++)
                        mma_f16(O[mi][nd], pa[mi], &vb[nd][2 * g]);
                // l column (constant ones fragment, no load)
#pragma unroll
                for (int mi = 0; mi < 2; mi++)
                    mma_f16(O[mi][4], pa[mi], onesb);
            }
        }
        __syncthreads();
        b ^= 1;
    }

    float* part = g_part[sp];
#pragma unroll
    for (int mi = 0; mi < 2; mi++) {
        const int r0 = q0 + w * 32 + mi * 16 + gid;
        if (tig == 0) {
            g_lpart[sp * HH * NN + h * NN + r0] = O[mi][4][0];
            g_lpart[sp * HH * NN + h * NN + r0 + 8] = O[mi][4][2];
        }
#pragma unroll
        for (int nd = 0; nd < 4; nd++) {
            const int col = h * DD + nd * 8 + 2 * tig;
            *(float2*)&part[(size_t)r0 * CC + col] = make_float2(O[mi][nd][0], O[mi][nd][1]);
            *(float2*)&part[(size_t)(r0 + 8) * CC + col] = make_float2(O[mi][nd][2], O[mi][nd][3]);
        }
    }
}

// ---------------- Kernel 3: mma out-proj + residual + LayerNorm ----------------
#define PMS_STR 132
#define PBS_STR 12

__global__ void __launch_bounds__(256) proj_mma_kernel(
    const float* __restrict__ x, const float* __restrict__ bo,
    const float* __restrict__ gamma, const float* __restrict__ beta,
    float* __restrict__ out)
{
    __shared__ uint32_t MS[32 * PMS_STR];
    __shared__ uint32_t BS[2][CC * PBS_STR];
    __shared__ float red[2][4][16][2];

    const int tid = threadIdx.x;
    const int w = tid >> 5;
    const int lane = tid & 31;
    const int gid = lane >> 2;
    const int tig = lane & 3;
    const int mh = w & 1;
    const int nw = w >> 1;
    const int m0 = mh * 16;
    const int n0 = nw * 64;
    const int row0 = blockIdx.x * 32;

    const uint32_t msb = (uint32_t)__cvta_generic_to_shared(MS);
    const uint32_t bsb = (uint32_t)__cvta_generic_to_shared(BS);
    const __half* Wg = &g_wt[3 * CC * CC];

    {
        uint32_t db = bsb + tid * PBS_STR * 4;
        cpa16(db, Wg + (size_t)tid * CC);
        cpa16(db + 16, Wg + (size_t)tid * CC + 8);
        CP_COMMIT();
    }

    for (int f = tid; f < 32 * 64; f += 256) {
        const int r = f >> 6;
        const int cq = (f & 63) * 4;
        const int node = row0 + r;
        const int h = cq >> 5;
        const float rl = 1.f / (g_lpart[h * NN + node] + g_lpart[HH * NN + h * NN + node]);
        float4 a = *(const float4*)&g_part[0][(size_t)node * CC + cq];
        float4 b4 = *(const float4*)&g_part[1][(size_t)node * CC + cq];
        MS[r * PMS_STR + cq / 2]     = f16pack((a.x + b4.x) * rl, (a.y + b4.y) * rl);
        MS[r * PMS_STR + cq / 2 + 1] = f16pack((a.z + b4.z) * rl, (a.w + b4.w) * rl);
    }

    float acc[8][4] = {};
    int b = 0;
    for (int it = 0; it < 16; it++) {
        if (it < 15) {
            const int kn = (it + 1) * 16;
            uint32_t db = bsb + ((b ^ 1) * CC * PBS_STR + tid * PBS_STR) * 4;
            cpa16(db, Wg + (size_t)tid * CC + kn);
            cpa16(db + 16, Wg + (size_t)tid * CC + kn + 8);
            CP_COMMIT();
            CP_WAIT(1);
        } else {
            CP_WAIT(0);
        }
        __syncthreads();

        uint32_t a[4];
        ldmx4(a, msb + ((m0 + (lane & 15)) * PMS_STR + it * 8 + (lane >> 4) * 4) * 4);

        uint32_t bf[4][4];
#pragma unroll
        for (int nj = 0; nj < 4; nj++)
            ldmx4(bf[nj], bsb + (b * CC * PBS_STR
                                 + (n0 + nj * 16 + (lane & 7) + (lane >> 4) * 8) * PBS_STR
                                 + ((lane >> 3) & 1) * 4) * 4);
#pragma unroll
        for (int nj = 0; nj < 4; nj++) {
            mma_f16(acc[2 * nj],     a, &bf[nj][0]);
            mma_f16(acc[2 * nj + 1], a, &bf[nj][2]);
        }
        __syncthreads();
        b ^= 1;
    }

    const int node0 = row0 + m0;
    float y[8][4];
    float s0 = 0.f, q0s = 0.f, s1 = 0.f, q1s = 0.f;
#pragma unroll
    for (int ni = 0; ni < 8; ni++) {
        const int c0 = n0 + ni * 8 + 2 * tig;
        float2 x0 = *(const float2*)&x[(size_t)(node0 + gid) * CC + c0];
        float2 x1 = *(const float2*)&x[(size_t)(node0 + gid + 8) * CC + c0];
        const float b0 = bo[c0], b1 = bo[c0 + 1];
        y[ni][0] = acc[ni][0] + b0 + x0.x;
        y[ni][1] = acc[ni][1] + b1 + x0.y;
        y[ni][2] = acc[ni][2] + b0 + x1.x;
        y[ni][3] = acc[ni][3] + b1 + x1.y;
        s0 += y[ni][0] + y[ni][1];
        s1 += y[ni][2] + y[ni][3];
        q0s = fmaf(y[ni][0], y[ni][0], fmaf(y[ni][1], y[ni][1], q0s));
        q1s = fmaf(y[ni][2], y[ni][2], fmaf(y[ni][3], y[ni][3], q1s));
    }
#pragma unroll
    for (int off = 1; off <= 2; off <<= 1) {
        s0 += __shfl_xor_sync(0xffffffffu, s0, off);
        s1 += __shfl_xor_sync(0xffffffffu, s1, off);
        q0s += __shfl_xor_sync(0xffffffffu, q0s, off);
        q1s += __shfl_xor_sync(0xffffffffu, q1s, off);
    }
    if (tig == 0) {
        red[mh][nw][gid][0] = s0;     red[mh][nw][gid][1] = q0s;
        red[mh][nw][gid + 8][0] = s1; red[mh][nw][gid + 8][1] = q1s;
    }
    __syncthreads();
    float sum0 = 0.f, sq0 = 0.f, sum1 = 0.f, sq1 = 0.f;
#pragma unroll
    for (int j = 0; j < 4; j++) {
        sum0 += red[mh][j][gid][0];     sq0 += red[mh][j][gid][1];
        sum1 += red[mh][j][gid + 8][0]; sq1 += red[mh][j][gid + 8][1];
    }
    const float mu0 = sum0 * (1.f / 256.f);
    const float mu1 = sum1 * (1.f / 256.f);
    const float rs0 = rsqrtf(sq0 * (1.f / 256.f) - mu0 * mu0 + 1e-5f);
    const float rs1 = rsqrtf(sq1 * (1.f / 256.f) - mu1 * mu1 + 1e-5f);
#pragma unroll
    for (int ni = 0; ni < 8; ni++) {
        const int c0 = n0 + ni * 8 + 2 * tig;
        const float g0 = gamma[c0], g1 = gamma[c0 + 1];
        const float be0 = beta[c0], be1 = beta[c0 + 1];
        *(float2*)&out[(size_t)(node0 + gid) * CC + c0] =
            make_float2((y[ni][0] - mu0) * rs0 * g0 + be0,
                        (y[ni][1] - mu0) * rs0 * g1 + be1);
        *(float2*)&out[(size_t)(node0 + gid + 8) * CC + c0] =
            make_float2((y[ni][2] - mu1) * rs1 * g0 + be0,
                        (y[ni][3] - mu1) * rs1 * g1 + be1);
    }
}

// ---------------- launch ----------------
extern "C" void kernel_launch(void* const* d_in, const int* in_sizes, int n_in,
                              void* d_out, int out_size)
{
    const float* x     = (const float*)d_in[0];
    const float* Wq    = (const float*)d_in[1];
    const float* bq    = (const float*)d_in[2];
    const float* Wk    = (const float*)d_in[3];
    const float* bk    = (const float*)d_in[4];
    const float* Wv    = (const float*)d_in[5];
    const float* bv    = (const float*)d_in[6];
    const float* scale = (const float*)d_in[7];
    const float* Wo    = (const float*)d_in[8];
    const float* bo    = (const float*)d_in[9];
    const float* gamma = (const float*)d_in[10];
    const float* beta  = (const float*)d_in[11];
    float* out = (float*)d_out;

    cvt_x_kernel<<<NN * CC / 1024, 256>>>(x);
    cvt_w_kernel<<<dim3(8, 8, 4), 256>>>(Wq, Wk, Wv, Wo);
    qkv_mma_kernel<<<dim3(CC / 64, NN / 64, 3), 128>>>(bq, bk, bv, scale);
    attn_mma_kernel<<<dim3(NN / QT, HH, SPLIT), 128>>>();
    proj_mma_kernel<<<NN / 32, 256>>>(x, bo, gamma, beta, out);
}

// round 17
// speedup vs baseline: 1.1447x; 1.0621x over previous
#include <cuda_runtime.h>
#include <cuda_fp16.h>
#include <cstdint>

#define NN 4096
#define CC 256
#define HH 8
#define DD 32
#define LOG2E 1.4426950408889634f

// scratch (device globals; no allocation allowed)
__device__ __half g_xh[NN * CC];          // x in f16
__device__ __half g_wt[4 * CC * CC];      // Wq,Wk,Wv,Wo transposed [n][k], f16
__device__ __half g_qh[HH * NN * DD];     // prescaled by scale*log2e
__device__ __half g_kh[HH * NN * DD];
__device__ __half g_vh[HH * NN * DD];
__device__ float g_part[4][NN * CC];      // un-normalized partial O
__device__ float g_lpart[4 * HH * NN];    // partial softmax denominators

// ---------------- helpers ----------------
__device__ __forceinline__ uint32_t f16pack(float lo, float hi) {
    uint32_t r;
    asm("cvt.rn.f16x2.f32 %0, %1, %2;" : "=r"(r) : "f"(hi), "f"(lo));
    return r;
}
__device__ __forceinline__ uint32_t ex2_f16x2(uint32_t x) {
    uint32_t r;
    asm("ex2.approx.f16x2 %0, %1;" : "=r"(r) : "r"(x));
    return r;
}
__device__ __forceinline__ uint32_t hadd2(uint32_t a, uint32_t b) {
    uint32_t r;
    asm("add.rn.f16x2 %0, %1, %2;" : "=r"(r) : "r"(a), "r"(b));
    return r;
}
__device__ __forceinline__ float2 h2f2(uint32_t h) {
    float lo, hi;
    asm("{.reg .f16 a,b; mov.b32 {a,b}, %2; cvt.f32.f16 %0, a; cvt.f32.f16 %1, b;}"
        : "=f"(lo), "=f"(hi) : "r"(h));
    return make_float2(lo, hi);
}
__device__ __forceinline__ void mma_f16(float* d, const uint32_t* a, const uint32_t* b) {
    asm volatile(
        "mma.sync.aligned.m16n8k16.row.col.f32.f16.f16.f32 "
        "{%0,%1,%2,%3}, {%4,%5,%6,%7}, {%8,%9}, {%0,%1,%2,%3};"
        : "+f"(d[0]), "+f"(d[1]), "+f"(d[2]), "+f"(d[3])
        : "r"(a[0]), "r"(a[1]), "r"(a[2]), "r"(a[3]), "r"(b[0]), "r"(b[1]));
}
__device__ __forceinline__ void ldmx4(uint32_t* r, uint32_t addr) {
    asm volatile("ldmatrix.sync.aligned.m8n8.x4.shared.b16 {%0,%1,%2,%3}, [%4];"
        : "=r"(r[0]), "=r"(r[1]), "=r"(r[2]), "=r"(r[3]) : "r"(addr));
}
__device__ __forceinline__ void ldmx4t(uint32_t* r, uint32_t addr) {
    asm volatile("ldmatrix.sync.aligned.m8n8.x4.trans.shared.b16 {%0,%1,%2,%3}, [%4];"
        : "=r"(r[0]), "=r"(r[1]), "=r"(r[2]), "=r"(r[3]) : "r"(addr));
}
__device__ __forceinline__ void cpa16(uint32_t d, const void* s) {
    asm volatile("{ .reg .u64 g; cvta.to.global.u64 g, %1; "
                 "cp.async.ca.shared.global [%0], [g], 16; }"
                 :: "r"(d), "l"(s) : "memory");
}
#define CP_COMMIT() asm volatile("cp.async.commit_group;" ::: "memory")
#define CP_WAIT(n)  asm volatile("cp.async.wait_group %0;" :: "n"(n) : "memory")

// ---------------- Kernel 0a: convert x -> f16 ----------------
__global__ void __launch_bounds__(256) cvt_x_kernel(const float* __restrict__ x)
{
    const int i = (blockIdx.x * 256 + threadIdx.x) * 4;
    float4 v = *(const float4*)&x[i];
    uint2 o;
    o.x = f16pack(v.x, v.y);
    o.y = f16pack(v.z, v.w);
    *(uint2*)&g_xh[i] = o;
}

// ---------------- Kernel 0b: transpose-convert W -> f16 [n][k] ----------------
__global__ void __launch_bounds__(256) cvt_w_kernel(
    const float* __restrict__ Wq, const float* __restrict__ Wk,
    const float* __restrict__ Wv, const float* __restrict__ Wo)
{
    __shared__ float t[32][33];
    const int z = blockIdx.z;
    const float* W = (z == 0) ? Wq : (z == 1) ? Wk : (z == 2) ? Wv : Wo;
    const int k0 = blockIdx.y * 32, n0 = blockIdx.x * 32;
    const int tx = threadIdx.x & 31, ty = threadIdx.x >> 5;  // 32x8
#pragma unroll
    for (int i = 0; i < 4; i++)
        t[ty + 8 * i][tx] = W[(size_t)(k0 + ty + 8 * i) * CC + n0 + tx];
    __syncthreads();
    __half* out = &g_wt[(size_t)z * CC * CC];
#pragma unroll
    for (int i = 0; i < 4; i++)
        out[(size_t)(n0 + ty + 8 * i) * CC + k0 + tx] = __float2half(t[tx][ty + 8 * i]);
}

// ---------------- Kernel 1: f16 mma QKV GEMM, cp.async pipelined ----------------
#define QSTR 20

__global__ void __launch_bounds__(128) qkv_mma_kernel(
    const float* __restrict__ bq, const float* __restrict__ bk,
    const float* __restrict__ bv, const float* __restrict__ scale_p)
{
    __shared__ uint32_t As[2][64 * QSTR];
    __shared__ uint32_t Bs[2][64 * QSTR];

    const int z = blockIdx.z;
    const float* bia = (z == 0) ? bq : (z == 1) ? bk : bv;
    __half* out = (z == 0) ? g_qh : (z == 1) ? g_kh : g_vh;
    const float s = (z == 0) ? (*scale_p) * LOG2E : 1.0f;

    const int row0 = blockIdx.y * 64;
    const int col0 = blockIdx.x * 64;
    const int tid = threadIdx.x;
    const int w = tid >> 5;
    const int lane = tid & 31;
    const int gid = lane >> 2;
    const int tig = lane & 3;
    const int m0 = (w & 1) * 32;
    const int n0 = (w >> 1) * 32;

    const __half* Ag = &g_xh[(size_t)row0 * CC];
    const __half* Bg = &g_wt[(size_t)z * CC * CC + (size_t)col0 * CC];
    const uint32_t asb = (uint32_t)__cvta_generic_to_shared(As);
    const uint32_t bsb = (uint32_t)__cvta_generic_to_shared(Bs);

    const int sr = tid >> 1, sc = tid & 1;
    float acc[2][4][4] = {};

    {
        uint32_t da = asb + (sr * QSTR + sc * 8) * 4;
        cpa16(da, Ag + sr * CC + sc * 16);
        cpa16(da + 16, Ag + sr * CC + sc * 16 + 8);
        uint32_t db = bsb + (sr * QSTR + sc * 8) * 4;
        cpa16(db, Bg + sr * CC + sc * 16);
        cpa16(db + 16, Bg + sr * CC + sc * 16 + 8);
        CP_COMMIT();
    }

    int b = 0;
    for (int it = 0; it < 8; it++) {
        if (it < 7) {
            const int kn = (it + 1) * 32;
            uint32_t da = asb + ((b ^ 1) * 64 * QSTR + sr * QSTR + sc * 8) * 4;
            cpa16(da, Ag + sr * CC + kn + sc * 16);
            cpa16(da + 16, Ag + sr * CC + kn + sc * 16 + 8);
            uint32_t db = bsb + ((b ^ 1) * 64 * QSTR + sr * QSTR + sc * 8) * 4;
            cpa16(db, Bg + sr * CC + kn + sc * 16);
            cpa16(db + 16, Bg + sr * CC + kn + sc * 16 + 8);
            CP_COMMIT();
            CP_WAIT(1);
        } else {
            CP_WAIT(0);
        }
        __syncthreads();

        uint32_t a[2][2][4];
#pragma unroll
        for (int mi = 0; mi < 2; mi++)
#pragma unroll
            for (int ks = 0; ks < 2; ks++)
                ldmx4(a[mi][ks], asb + (b * 64 * QSTR + (m0 + mi * 16 + (lane & 15)) * QSTR
                                        + ks * 8 + (lane >> 4) * 4) * 4);
        uint32_t bf[4][4];
#pragma unroll
        for (int ni = 0; ni < 4; ni++)
            ldmx4(bf[ni], bsb + (b * 64 * QSTR + (n0 + ni * 8 + (lane & 7)) * QSTR
                                 + (lane >> 3) * 4) * 4);
#pragma unroll
        for (int ks = 0; ks < 2; ks++)
#pragma unroll
            for (int mi = 0; mi < 2; mi++)
#pragma unroll
                for (int ni = 0; ni < 4; ni++)
                    mma_f16(acc[mi][ni], a[mi][ks], &bf[ni][2 * ks]);
        __syncthreads();
        b ^= 1;
    }

#pragma unroll
    for (int mi = 0; mi < 2; mi++) {
        const int row = row0 + m0 + mi * 16 + gid;
#pragma unroll
        for (int ni = 0; ni < 4; ni++) {
            const int col = col0 + n0 + ni * 8 + 2 * tig;
            const int h = col >> 5, d = col & 31;
            const float b0 = bia[col], b1 = bia[col + 1];
            uint32_t w0 = f16pack((acc[mi][ni][0] + b0) * s, (acc[mi][ni][1] + b1) * s);
            uint32_t w1 = f16pack((acc[mi][ni][2] + b0) * s, (acc[mi][ni][3] + b1) * s);
            *(uint32_t*)&out[((size_t)h * NN + row) * DD + d] = w0;
            *(uint32_t*)&out[((size_t)h * NN + row + 8) * DD + d] = w1;
        }
    }
}

// ---------------- Kernel 2: f16 mma flash attention, split-K=4 ----------------
// K|V interleaved XOR-swizzled rows, 32KB double-buffered smem, 4 CTAs/SM.
// SPLIT=4 for load balance (1024 CTAs, 8 chunks each). l via HADD2 on alu pipe.
#define QT 128
#define KT 128
#define NCHUNK (NN / KT)
#define SPLIT 4
#define NITER (NCHUNK / SPLIT)

__global__ void __launch_bounds__(128, 4) attn_mma_kernel()
{
    __shared__ uint32_t KV[2][KT * 32];   // 2 x 16KB

    const int tid = threadIdx.x;
    const int w = tid >> 5;
    const int lane = tid & 31;
    const int gid = lane >> 2;
    const int tig = lane & 3;
    const int h = blockIdx.y;
    const int q0 = blockIdx.x * QT;
    const int sp = blockIdx.z;

    const uint32_t kvb = (uint32_t)__cvta_generic_to_shared(KV);

    const __half* Kg = &g_kh[((size_t)h * NN + tid) * DD];
    const __half* Vg = &g_vh[((size_t)h * NN + tid) * DD];
    const uint32_t rowdst = kvb + tid * 128;
    const int rsw = tid & 7;

    // Q fragments (f16, scale*log2e folded)
    uint32_t qa[2][2][4];
#pragma unroll
    for (int mi = 0; mi < 2; mi++) {
        const int r0 = q0 + w * 32 + mi * 16 + gid;
        const uint32_t* p0 = (const uint32_t*)&g_qh[((size_t)h * NN + r0) * DD];
        const uint32_t* p1 = (const uint32_t*)&g_qh[((size_t)h * NN + r0 + 8) * DD];
#pragma unroll
        for (int ks = 0; ks < 2; ks++) {
            qa[mi][ks][0] = p0[8 * ks + tig];
            qa[mi][ks][1] = p1[8 * ks + tig];
            qa[mi][ks][2] = p0[8 * ks + tig + 4];
            qa[mi][ks][3] = p1[8 * ks + tig + 4];
        }
    }

    // prologue: stage chunk sp into buf 0
    {
        const size_t off = (size_t)sp * KT * DD;
#pragma unroll
        for (int c = 0; c < 4; c++) {
            cpa16(rowdst + ((c ^ rsw) << 4), Kg + off + 8 * c);
            cpa16(rowdst + (((4 + c) ^ rsw) << 4), Vg + off + 8 * c);
        }
        CP_COMMIT();
    }

    float O[2][4][4] = {};
    float lf[2][2] = {};
    int b = 0;

    for (int it = 0; it < NITER; it++) {
        if (it < NITER - 1) {
            const size_t off = (size_t)(sp + (it + 1) * SPLIT) * KT * DD;
            const uint32_t bo2 = rowdst + (b ^ 1) * (KT * 32 * 4);
#pragma unroll
            for (int c = 0; c < 4; c++) {
                cpa16(bo2 + ((c ^ rsw) << 4), Kg + off + 8 * c);
                cpa16(bo2 + (((4 + c) ^ rsw) << 4), Vg + off + 8 * c);
            }
            CP_COMMIT();
            CP_WAIT(1);
        } else {
            CP_WAIT(0);
        }
        __syncthreads();

        const uint32_t base = kvb + b * (KT * 32 * 4);
        uint32_t lc[2][2] = {{0u, 0u}, {0u, 0u}};  // per-chunk f16x2 l accum

#pragma unroll
        for (int sub = 0; sub < 4; sub++) {
            const int n0 = sub * 32;

            // K fragments: 4 matrices (16B chunks 0-3), rows = keys
            uint32_t kb[4][4];
#pragma unroll
            for (int ni = 0; ni < 4; ni++) {
                const int kr = n0 + ni * 8 + (lane & 7);
                ldmx4(kb[ni], base + kr * 128 + (((lane >> 3) ^ (kr & 7)) << 4));
            }

            // per-mi: S then immediately ex2 -> ep (halves live S registers)
            uint32_t ep[2][4][2];
#pragma unroll
            for (int mi = 0; mi < 2; mi++) {
                float S[4][4] = {};
#pragma unroll
                for (int ks = 0; ks < 2; ks++)
#pragma unroll
                    for (int ni = 0; ni < 4; ni++)
                        mma_f16(S[ni], qa[mi][ks], &kb[ni][2 * ks]);
#pragma unroll
                for (int ni = 0; ni < 4; ni++) {
                    ep[mi][ni][0] = ex2_f16x2(f16pack(S[ni][0], S[ni][1]));
                    ep[mi][ni][1] = ex2_f16x2(f16pack(S[ni][2], S[ni][3]));
                }
                // l on the alu pipe
                lc[mi][0] = hadd2(lc[mi][0],
                                  hadd2(hadd2(ep[mi][0][0], ep[mi][1][0]),
                                        hadd2(ep[mi][2][0], ep[mi][3][0])));
                lc[mi][1] = hadd2(lc[mi][1],
                                  hadd2(hadd2(ep[mi][0][1], ep[mi][1][1]),
                                        hadd2(ep[mi][2][1], ep[mi][3][1])));
            }

            // V^T fragments (trans): V chunk nd at logical 4+nd, rows = keys
            uint32_t vb[4][4];
#pragma unroll
            for (int nd = 0; nd < 4; nd++) {
                const int vr = n0 + lane;
                ldmx4t(vb[nd], base + vr * 128 + ((((4 + nd)) ^ (vr & 7)) << 4));
            }

#pragma unroll
            for (int g = 0; g < 2; g++) {
                uint32_t pa[2][4];
#pragma unroll
                for (int mi = 0; mi < 2; mi++) {
                    pa[mi][0] = ep[mi][2 * g][0];
                    pa[mi][1] = ep[mi][2 * g][1];
                    pa[mi][2] = ep[mi][2 * g + 1][0];
                    pa[mi][3] = ep[mi][2 * g + 1][1];
                }
#pragma unroll
                for (int nd = 0; nd < 4; nd++)
#pragma unroll
                    for (int mi = 0; mi < 2; mi++)
                        mma_f16(O[mi][nd], pa[mi], &vb[nd][2 * g]);
            }
        }

        // upconvert per-chunk l to f32
#pragma unroll
        for (int mi = 0; mi < 2; mi++) {
            float2 a0 = h2f2(lc[mi][0]);
            float2 a1 = h2f2(lc[mi][1]);
            lf[mi][0] += a0.x + a0.y;
            lf[mi][1] += a1.x + a1.y;
        }

        __syncthreads();
        b ^= 1;
    }

    // reduce l over tig (4 threads per row cover disjoint key columns)
#pragma unroll
    for (int mi = 0; mi < 2; mi++)
#pragma unroll
        for (int hf = 0; hf < 2; hf++) {
            float v = lf[mi][hf];
            v += __shfl_xor_sync(0xffffffffu, v, 1);
            v += __shfl_xor_sync(0xffffffffu, v, 2);
            lf[mi][hf] = v;
        }

    float* part = g_part[sp];
#pragma unroll
    for (int mi = 0; mi < 2; mi++) {
        const int r0 = q0 + w * 32 + mi * 16 + gid;
        if (tig == 0) {
            g_lpart[sp * HH * NN + h * NN + r0] = lf[mi][0];
            g_lpart[sp * HH * NN + h * NN + r0 + 8] = lf[mi][1];
        }
#pragma unroll
        for (int nd = 0; nd < 4; nd++) {
            const int col = h * DD + nd * 8 + 2 * tig;
            *(float2*)&part[(size_t)r0 * CC + col] = make_float2(O[mi][nd][0], O[mi][nd][1]);
            *(float2*)&part[(size_t)(r0 + 8) * CC + col] = make_float2(O[mi][nd][2], O[mi][nd][3]);
        }
    }
}

// ---------------- Kernel 3: mma out-proj + residual + LayerNorm ----------------
#define PMS_STR 132
#define PBS_STR 12

__global__ void __launch_bounds__(256) proj_mma_kernel(
    const float* __restrict__ x, const float* __restrict__ bo,
    const float* __restrict__ gamma, const float* __restrict__ beta,
    float* __restrict__ out)
{
    __shared__ uint32_t MS[32 * PMS_STR];
    __shared__ uint32_t BS[2][CC * PBS_STR];
    __shared__ float red[2][4][16][2];

    const int tid = threadIdx.x;
    const int w = tid >> 5;
    const int lane = tid & 31;
    const int gid = lane >> 2;
    const int tig = lane & 3;
    const int mh = w & 1;
    const int nw = w >> 1;
    const int m0 = mh * 16;
    const int n0 = nw * 64;
    const int row0 = blockIdx.x * 32;

    const uint32_t msb = (uint32_t)__cvta_generic_to_shared(MS);
    const uint32_t bsb = (uint32_t)__cvta_generic_to_shared(BS);
    const __half* Wg = &g_wt[3 * CC * CC];

    {
        uint32_t db = bsb + tid * PBS_STR * 4;
        cpa16(db, Wg + (size_t)tid * CC);
        cpa16(db + 16, Wg + (size_t)tid * CC + 8);
        CP_COMMIT();
    }

    // combine 4 split partials + normalize -> f16
    for (int f = tid; f < 32 * 64; f += 256) {
        const int r = f >> 6;
        const int cq = (f & 63) * 4;
        const int node = row0 + r;
        const int h = cq >> 5;
        const int li = h * NN + node;
        const float rl = 1.f / (g_lpart[li] + g_lpart[HH * NN + li]
                                + g_lpart[2 * HH * NN + li] + g_lpart[3 * HH * NN + li]);
        float4 a = *(const float4*)&g_part[0][(size_t)node * CC + cq];
        float4 b4 = *(const float4*)&g_part[1][(size_t)node * CC + cq];
        float4 c4 = *(const float4*)&g_part[2][(size_t)node * CC + cq];
        float4 d4 = *(const float4*)&g_part[3][(size_t)node * CC + cq];
        MS[r * PMS_STR + cq / 2]     = f16pack((a.x + b4.x + c4.x + d4.x) * rl,
                                               (a.y + b4.y + c4.y + d4.y) * rl);
        MS[r * PMS_STR + cq / 2 + 1] = f16pack((a.z + b4.z + c4.z + d4.z) * rl,
                                               (a.w + b4.w + c4.w + d4.w) * rl);
    }

    float acc[8][4] = {};
    int b = 0;
    for (int it = 0; it < 16; it++) {
        if (it < 15) {
            const int kn = (it + 1) * 16;
            uint32_t db = bsb + ((b ^ 1) * CC * PBS_STR + tid * PBS_STR) * 4;
            cpa16(db, Wg + (size_t)tid * CC + kn);
            cpa16(db + 16, Wg + (size_t)tid * CC + kn + 8);
            CP_COMMIT();
            CP_WAIT(1);
        } else {
            CP_WAIT(0);
        }
        __syncthreads();

        uint32_t a[4];
        ldmx4(a, msb + ((m0 + (lane & 15)) * PMS_STR + it * 8 + (lane >> 4) * 4) * 4);

        uint32_t bf[4][4];
#pragma unroll
        for (int nj = 0; nj < 4; nj++)
            ldmx4(bf[nj], bsb + (b * CC * PBS_STR
                                 + (n0 + nj * 16 + (lane & 7) + (lane >> 4) * 8) * PBS_STR
                                 + ((lane >> 3) & 1) * 4) * 4);
#pragma unroll
        for (int nj = 0; nj < 4; nj++) {
            mma_f16(acc[2 * nj],     a, &bf[nj][0]);
            mma_f16(acc[2 * nj + 1], a, &bf[nj][2]);
        }
        __syncthreads();
        b ^= 1;
    }

    const int node0 = row0 + m0;
    float y[8][4];
    float s0 = 0.f, q0s = 0.f, s1 = 0.f, q1s = 0.f;
#pragma unroll
    for (int ni = 0; ni < 8; ni++) {
        const int c0 = n0 + ni * 8 + 2 * tig;
        float2 x0 = *(const float2*)&x[(size_t)(node0 + gid) * CC + c0];
        float2 x1 = *(const float2*)&x[(size_t)(node0 + gid + 8) * CC + c0];
        const float b0 = bo[c0], b1 = bo[c0 + 1];
        y[ni][0] = acc[ni][0] + b0 + x0.x;
        y[ni][1] = acc[ni][1] + b1 + x0.y;
        y[ni][2] = acc[ni][2] + b0 + x1.x;
        y[ni][3] = acc[ni][3] + b1 + x1.y;
        s0 += y[ni][0] + y[ni][1];
        s1 += y[ni][2] + y[ni][3];
        q0s = fmaf(y[ni][0], y[ni][0], fmaf(y[ni][1], y[ni][1], q0s));
        q1s = fmaf(y[ni][2], y[ni][2], fmaf(y[ni][3], y[ni][3], q1s));
    }
#pragma unroll
    for (int off = 1; off <= 2; off <<= 1) {
        s0 += __shfl_xor_sync(0xffffffffu, s0, off);
        s1 += __shfl_xor_sync(0xffffffffu, s1, off);
        q0s += __shfl_xor_sync(0xffffffffu, q0s, off);
        q1s += __shfl_xor_sync(0xffffffffu, q1s, off);
    }
    if (tig == 0) {
        red[mh][nw][gid][0] = s0;     red[mh][nw][gid][1] = q0s;
        red[mh][nw][gid + 8][0] = s1; red[mh][nw][gid + 8][1] = q1s;
    }
    __syncthreads();
    float sum0 = 0.f, sq0 = 0.f, sum1 = 0.f, sq1 = 0.f;
#pragma unroll
    for (int j = 0; j < 4; j++) {
        sum0 += red[mh][j][gid][0];     sq0 += red[mh][j][gid][1];
        sum1 += red[mh][j][gid + 8][0]; sq1 += red[mh][j][gid + 8][1];
    }
    const float mu0 = sum0 * (1.f / 256.f);
    const float mu1 = sum1 * (1.f / 256.f);
    const float rs0 = rsqrtf(sq0 * (1.f / 256.f) - mu0 * mu0 + 1e-5f);
    const float rs1 = rsqrtf(sq1 * (1.f / 256.f) - mu1 * mu1 + 1e-5f);
#pragma unroll
    for (int ni = 0; ni < 8; ni++) {
        const int c0 = n0 + ni * 8 + 2 * tig;
        const float g0 = gamma[c0], g1 = gamma[c0 + 1];
        const float be0 = beta[c0], be1 = beta[c0 + 1];
        *(float2*)&out[(size_t)(node0 + gid) * CC + c0] =
            make_float2((y[ni][0] - mu0) * rs0 * g0 + be0,
                        (y[ni][1] - mu0) * rs0 * g1 + be1);
        *(float2*)&out[(size_t)(node0 + gid + 8) * CC + c0] =
            make_float2((y[ni][2] - mu1) * rs1 * g0 + be0,
                        (y[ni][3] - mu1) * rs1 * g1 + be1);
    }
}

// ---------------- launch ----------------
extern "C" void kernel_launch(void* const* d_in, const int* in_sizes, int n_in,
                              void* d_out, int out_size)
{
    const float* x     = (const float*)d_in[0];
    const float* Wq    = (const float*)d_in[1];
    const float* bq    = (const float*)d_in[2];
    const float* Wk    = (const float*)d_in[3];
    const float* bk    = (const float*)d_in[4];
    const float* Wv    = (const float*)d_in[5];
    const float* bv    = (const float*)d_in[6];
    const float* scale = (const float*)d_in[7];
    const float* Wo    = (const float*)d_in[8];
    const float* bo    = (const float*)d_in[9];
    const float* gamma = (const float*)d_in[10];
    const float* beta  = (const float*)d_in[11];
    float* out = (float*)d_out;

    cvt_x_kernel<<<NN * CC / 1024, 256>>>(x);
    cvt_w_kernel<<<dim3(8, 8, 4), 256>>>(Wq, Wk, Wv, Wo);
    qkv_mma_kernel<<<dim3(CC / 64, NN / 64, 3), 128>>>(bq, bk, bv, scale);
    attn_mma_kernel<<<dim3(NN / QT, HH, SPLIT), 128>>>();
    proj_mma_kernel<<<NN / 32, 256>>>(x, bo, gamma, beta, out);
}